// round 2
// baseline (speedup 1.0000x reference)
#include <cuda_runtime.h>

// Problem constants
static constexpr int Bb = 4, T = 2048, D = 512, Hh = 8, HK = 64;
static constexpr int MROWS = Bb * T;          // 8192
static constexpr long QKV_STRIDE = 3 * D;     // 1536

// Scratch (device globals: allocation-free)
__device__ float g_qkv[MROWS * 3 * D];        // [8192, 1536]  (Q | K | V)
__device__ float g_attn[MROWS * D];           // [8192, 512]   (B,T,H*K)

// ---------------------------------------------------------------------------
// GEMM: C[M,N] = A[M,K] @ B[N,K]^T (+ bias[n]).  BM=BN=64, BK=16, 256 thr,
// 4x4 register tile per thread.
// ---------------------------------------------------------------------------
template<bool HAS_BIAS>
__global__ void gemm_nt_kernel(const float* __restrict__ A,
                               const float* __restrict__ Bm,
                               const float* __restrict__ bias,
                               float* __restrict__ C,
                               int M, int N, int K)
{
    constexpr int BM = 64, BN = 64, BK = 16;
    __shared__ __align__(16) float As[BK][BM + 4];
    __shared__ __align__(16) float Bs[BK][BN + 4];

    const int tid = threadIdx.x;
    const int tx = tid & 15;
    const int ty = tid >> 4;
    const int m0 = blockIdx.y * BM;
    const int n0 = blockIdx.x * BN;

    const int lr = tid >> 2;          // 0..63 tile row
    const int lk = (tid & 3) * 4;     // 0,4,8,12 k offset

    const float* Ap = A + (long)(m0 + lr) * K + lk;
    const float* Bp = Bm + (long)(n0 + lr) * K + lk;

    float acc[4][4] = {};

    for (int k0 = 0; k0 < K; k0 += BK) {
        float4 av = *(const float4*)(Ap + k0);
        float4 bv = *(const float4*)(Bp + k0);
        As[lk + 0][lr] = av.x; As[lk + 1][lr] = av.y;
        As[lk + 2][lr] = av.z; As[lk + 3][lr] = av.w;
        Bs[lk + 0][lr] = bv.x; Bs[lk + 1][lr] = bv.y;
        Bs[lk + 2][lr] = bv.z; Bs[lk + 3][lr] = bv.w;
        __syncthreads();
#pragma unroll
        for (int kk = 0; kk < BK; kk++) {
            float4 a4 = *(const float4*)&As[kk][ty * 4];
            float4 b4 = *(const float4*)&Bs[kk][tx * 4];
            float ar[4] = {a4.x, a4.y, a4.z, a4.w};
            float br[4] = {b4.x, b4.y, b4.z, b4.w};
#pragma unroll
            for (int i = 0; i < 4; i++)
#pragma unroll
                for (int j = 0; j < 4; j++)
                    acc[i][j] = fmaf(ar[i], br[j], acc[i][j]);
        }
        __syncthreads();
    }

    float4 bias4 = {0.f, 0.f, 0.f, 0.f};
    if (HAS_BIAS) bias4 = *(const float4*)(bias + n0 + tx * 4);

    float* Cp = C + (long)(m0 + ty * 4) * N + n0 + tx * 4;
#pragma unroll
    for (int i = 0; i < 4; i++) {
        float4 v;
        v.x = acc[i][0] + bias4.x;
        v.y = acc[i][1] + bias4.y;
        v.z = acc[i][2] + bias4.z;
        v.w = acc[i][3] + bias4.w;
        *(float4*)(Cp + (long)i * N) = v;
    }
}

// ---------------------------------------------------------------------------
// Flash attention (causal, head dim 64, fp32).
// Grid: (T/64, B*H). Block: 256 threads. 64-query tile per block.
// Smem: Qt[k][i], Kt[k][j], Vs[j][c], Ps[j][i]  -- each [64][68] fp32.
// Loader: each thread fills 4 float4s => full 64x64 tile (4096 floats).
// ---------------------------------------------------------------------------
__global__ void flash_attn_kernel(const float* __restrict__ qkv,
                                  float* __restrict__ attn_out)
{
    extern __shared__ __align__(16) float smem[];
    float (*Qt)[68] = (float(*)[68])(smem);
    float (*Kt)[68] = (float(*)[68])(smem + 64 * 68);
    float (*Vs)[68] = (float(*)[68])(smem + 2 * 64 * 68);
    float (*Ps)[68] = (float(*)[68])(smem + 3 * 64 * 68);

    const int tid = threadIdx.x;
    const int tx = tid & 15;
    const int ty = tid >> 4;
    const int bh = blockIdx.y;
    const int b = bh >> 3;
    const int h = bh & 7;
    const int q0 = blockIdx.x * 64;

    const float* base = qkv + (long)b * T * QKV_STRIDE + h * HK;

    const int lr = tid >> 2;              // 0..63 (row within tile)
    const int lc0 = (tid & 3) * 16;       // 0,16,32,48 (col group start)

    // Load Q tile transposed: Qt[k][i], full 64 cols
#pragma unroll
    for (int u = 0; u < 4; u++) {
        const int lc = lc0 + u * 4;
        float4 v = *(const float4*)(base + (long)(q0 + lr) * QKV_STRIDE + lc);
        Qt[lc + 0][lr] = v.x; Qt[lc + 1][lr] = v.y;
        Qt[lc + 2][lr] = v.z; Qt[lc + 3][lr] = v.w;
    }

    float m_i[4], l_i[4], o[4][4];
#pragma unroll
    for (int i = 0; i < 4; i++) {
        m_i[i] = -1e30f; l_i[i] = 0.f;
#pragma unroll
        for (int j = 0; j < 4; j++) o[i][j] = 0.f;
    }

    const float scale = 0.125f;  // 1/sqrt(64)
    const int ntiles = blockIdx.x + 1;

    for (int t0 = 0; t0 < ntiles; t0++) {
        const int j0 = t0 * 64;
        __syncthreads();   // protect Kt/Vs from previous iteration's readers
        {
            const float* kb = base + D;
            const float* vb = base + 2 * D;
#pragma unroll
            for (int u = 0; u < 4; u++) {
                const int lc = lc0 + u * 4;
                float4 kv = *(const float4*)(kb + (long)(j0 + lr) * QKV_STRIDE + lc);
                Kt[lc + 0][lr] = kv.x; Kt[lc + 1][lr] = kv.y;
                Kt[lc + 2][lr] = kv.z; Kt[lc + 3][lr] = kv.w;
                float4 vv = *(const float4*)(vb + (long)(j0 + lr) * QKV_STRIDE + lc);
                *(float4*)&Vs[lr][lc] = vv;
            }
        }
        __syncthreads();

        // S = Q @ K^T  (4x4 per thread)
        float s[4][4] = {};
#pragma unroll 8
        for (int kk = 0; kk < 64; kk++) {
            float4 a4 = *(const float4*)&Qt[kk][ty * 4];
            float4 b4 = *(const float4*)&Kt[kk][tx * 4];
            float ar[4] = {a4.x, a4.y, a4.z, a4.w};
            float br[4] = {b4.x, b4.y, b4.z, b4.w};
#pragma unroll
            for (int i = 0; i < 4; i++)
#pragma unroll
                for (int j = 0; j < 4; j++)
                    s[i][j] = fmaf(ar[i], br[j], s[i][j]);
        }

        const bool diag = (j0 == q0);
#pragma unroll
        for (int i = 0; i < 4; i++)
#pragma unroll
            for (int j = 0; j < 4; j++) {
                s[i][j] *= scale;
                if (diag && (tx * 4 + j > ty * 4 + i))
                    s[i][j] = -1e30f;
            }

        // Row max across the 16 lanes sharing a row (half-warp)
        float rmax[4], rsum[4], alpha[4];
#pragma unroll
        for (int i = 0; i < 4; i++) {
            float v = fmaxf(fmaxf(s[i][0], s[i][1]), fmaxf(s[i][2], s[i][3]));
#pragma unroll
            for (int d = 1; d < 16; d <<= 1)
                v = fmaxf(v, __shfl_xor_sync(0xffffffffu, v, d));
            rmax[i] = v;
        }
#pragma unroll
        for (int i = 0; i < 4; i++) {
            float nm = fmaxf(m_i[i], rmax[i]);
            alpha[i] = __expf(m_i[i] - nm);
            m_i[i] = nm;
        }
        // P = exp(S - m), row sum
#pragma unroll
        for (int i = 0; i < 4; i++) {
#pragma unroll
            for (int j = 0; j < 4; j++)
                s[i][j] = __expf(s[i][j] - m_i[i]);
            float v = s[i][0] + s[i][1] + s[i][2] + s[i][3];
#pragma unroll
            for (int d = 1; d < 16; d <<= 1)
                v += __shfl_xor_sync(0xffffffffu, v, d);
            rsum[i] = v;
        }
#pragma unroll
        for (int i = 0; i < 4; i++) {
            l_i[i] = l_i[i] * alpha[i] + rsum[i];
#pragma unroll
            for (int j = 0; j < 4; j++) {
                Ps[tx * 4 + j][ty * 4 + i] = s[i][j];  // transposed for P@V
                o[i][j] *= alpha[i];
            }
        }
        __syncthreads();

        // O += P @ V  (reduction over key index jj)
#pragma unroll 8
        for (int jj = 0; jj < 64; jj++) {
            float4 a4 = *(const float4*)&Ps[jj][ty * 4];
            float4 b4 = *(const float4*)&Vs[jj][tx * 4];
            float ar[4] = {a4.x, a4.y, a4.z, a4.w};
            float br[4] = {b4.x, b4.y, b4.z, b4.w};
#pragma unroll
            for (int i = 0; i < 4; i++)
#pragma unroll
                for (int j = 0; j < 4; j++)
                    o[i][j] = fmaf(ar[i], br[j], o[i][j]);
        }
    }

    // Epilogue: normalize and write [B,T,H*K]
    float* ob = attn_out + ((long)b * T + q0) * D + h * HK;
#pragma unroll
    for (int i = 0; i < 4; i++) {
        float inv = 1.f / l_i[i];
        float4 v = {o[i][0] * inv, o[i][1] * inv, o[i][2] * inv, o[i][3] * inv};
        *(float4*)(ob + (long)(ty * 4 + i) * D + tx * 4) = v;
    }
}

// ---------------------------------------------------------------------------
extern "C" void kernel_launch(void* const* d_in, const int* in_sizes, int n_in,
                              void* d_out, int out_size)
{
    (void)out_size;
    // Map inputs by element count (ordering-proof): all four sizes distinct.
    const float *x = nullptr, *w_qkv = nullptr, *w_proj = nullptr, *b_proj = nullptr;
    for (int i = 0; i < n_in; i++) {
        switch (in_sizes[i]) {
            case MROWS * D:      x      = (const float*)d_in[i]; break; // 4194304
            case 3 * D * D:      w_qkv  = (const float*)d_in[i]; break; // 786432
            case D * D:          w_proj = (const float*)d_in[i]; break; // 262144
            case D:              b_proj = (const float*)d_in[i]; break; // 512
        }
    }
    float* out = (float*)d_out;                    // [4,2048,512]

    float* qkv_buf = nullptr;
    float* attn_buf = nullptr;
    cudaGetSymbolAddress((void**)&qkv_buf, g_qkv);
    cudaGetSymbolAddress((void**)&attn_buf, g_attn);

    // 1) QKV projection: [8192,1536] = x @ w_qkv^T
    {
        dim3 grid(3 * D / 64, MROWS / 64);   // (24, 128)
        gemm_nt_kernel<false><<<grid, 256>>>(x, w_qkv, nullptr, qkv_buf,
                                             MROWS, 3 * D, D);
    }

    // 2) Causal flash attention
    {
        const int smem_bytes = 4 * 64 * 68 * (int)sizeof(float);  // 69632
        cudaFuncSetAttribute(flash_attn_kernel,
                             cudaFuncAttributeMaxDynamicSharedMemorySize,
                             smem_bytes);
        dim3 grid(T / 64, Bb * Hh);          // (32, 32)
        flash_attn_kernel<<<grid, 256, smem_bytes>>>(qkv_buf, attn_buf);
    }

    // 3) Output projection + bias: [8192,512] = attn @ w_proj^T + b
    {
        dim3 grid(D / 64, MROWS / 64);       // (8, 128)
        gemm_nt_kernel<true><<<grid, 256>>>(attn_buf, w_proj, b_proj, out,
                                            MROWS, D, D);
    }
}

// round 7
// speedup vs baseline: 3.5464x; 3.5464x over previous
#include <cuda_runtime.h>
#include <cstdint>

// Problem constants
static constexpr int Bb = 4, T = 2048, D = 512, Hh = 8, HK = 64;
static constexpr int MROWS = Bb * T;          // 8192
static constexpr long QKV_STRIDE = 3 * D;     // 1536

// Scratch (device globals: allocation-free)
__device__ float g_qkv[MROWS * 3 * D];        // [8192, 1536]  (Q | K | V)
__device__ float g_attn[MROWS * D];           // [8192, 512]   (B,T,H*K)

// ---------------------------------------------------------------------------
// Helpers (baseline PTX only — no 'a'-suffix ISA)
// ---------------------------------------------------------------------------
__device__ __forceinline__ uint32_t tf32r(float f) {
    uint32_t u;
    asm("cvt.rna.tf32.f32 %0, %1;" : "=r"(u) : "f"(f));
    return u;
}
__device__ __forceinline__ void mma_tf32(float* c, const uint32_t* a,
                                         uint32_t b0, uint32_t b1) {
    asm volatile(
        "mma.sync.aligned.m16n8k8.row.col.f32.tf32.tf32.f32 "
        "{%0,%1,%2,%3}, {%4,%5,%6,%7}, {%8,%9}, {%0,%1,%2,%3};"
        : "+f"(c[0]), "+f"(c[1]), "+f"(c[2]), "+f"(c[3])
        : "r"(a[0]), "r"(a[1]), "r"(a[2]), "r"(a[3]), "r"(b0), "r"(b1));
}

// ---------------------------------------------------------------------------
// tf32 mma.sync GEMM: C[M,N] = A[M,512] @ B[N,512]^T (+bias).
// 128x128 tile, 256 thr = 8 warps (4 m x 2 n), warp tile 32x64.
// BK=32, double-buffered smem (pad 36), register prefetch.
// ---------------------------------------------------------------------------
template<bool HAS_BIAS>
__global__ void __launch_bounds__(256)
gemm_mma_kernel(const float* __restrict__ A, const float* __restrict__ Bw,
                const float* __restrict__ bias, float* __restrict__ C, int N)
{
    extern __shared__ uint32_t sm[];
    constexpr int PAD = 36;                 // 36 words/row: conflict-free frags
    uint32_t* const A0 = sm;                // stage area: [2][128][36]
    uint32_t* const B0 = sm + 2 * 128 * PAD;

    const int tid = threadIdx.x, lane = tid & 31, w = tid >> 5;
    const int mw = w & 3, nw = w >> 2;
    const int m0 = blockIdx.y * 128, n0 = blockIdx.x * 128;
    const int r = lane >> 2, cq = lane & 3;

    // Loader mapping: c4 = tid&7 (const), rows tid>>3 + 32*i
    const int c4 = tid & 7, row_b = tid >> 3;
    const float* Ag = A + (long)(m0 + row_b) * 512 + c4 * 4;
    const float* Bg = Bw + (long)(n0 + row_b) * 512 + c4 * 4;

    float acc[2][8][4] = {};
    float4 ra[4], rb[4];

    // chunk 0: load + store
#pragma unroll
    for (int i = 0; i < 4; i++) {
        ra[i] = *(const float4*)(Ag + (long)(32 * i) * 512);
        rb[i] = *(const float4*)(Bg + (long)(32 * i) * 512);
    }
#pragma unroll
    for (int i = 0; i < 4; i++) {
        uint4 ua = {tf32r(ra[i].x), tf32r(ra[i].y), tf32r(ra[i].z), tf32r(ra[i].w)};
        *(uint4*)&A0[(row_b + 32 * i) * PAD + c4 * 4] = ua;
        uint4 ub = {tf32r(rb[i].x), tf32r(rb[i].y), tf32r(rb[i].z), tf32r(rb[i].w)};
        *(uint4*)&B0[(row_b + 32 * i) * PAD + c4 * 4] = ub;
    }
    __syncthreads();
    // prefetch chunk 1
#pragma unroll
    for (int i = 0; i < 4; i++) {
        ra[i] = *(const float4*)(Ag + (long)(32 * i) * 512 + 32);
        rb[i] = *(const float4*)(Bg + (long)(32 * i) * 512 + 32);
    }

    for (int ch = 0; ch < 16; ch++) {
        const uint32_t* as = A0 + (ch & 1) * 128 * PAD;
        const uint32_t* bs = B0 + (ch & 1) * 128 * PAD;
#pragma unroll
        for (int kt = 0; kt < 4; kt++) {
            const int k0 = kt * 8;
            uint32_t af[2][4];
#pragma unroll
            for (int mt = 0; mt < 2; mt++) {
                const int rr = mw * 32 + mt * 16 + r;
                af[mt][0] = as[rr * PAD + k0 + cq];
                af[mt][1] = as[(rr + 8) * PAD + k0 + cq];
                af[mt][2] = as[rr * PAD + k0 + cq + 4];
                af[mt][3] = as[(rr + 8) * PAD + k0 + cq + 4];
            }
            uint32_t bf[8][2];
#pragma unroll
            for (int t = 0; t < 8; t++) {
                const int nr = nw * 64 + t * 8 + r;
                bf[t][0] = bs[nr * PAD + k0 + cq];
                bf[t][1] = bs[nr * PAD + k0 + cq + 4];
            }
#pragma unroll
            for (int mt = 0; mt < 2; mt++)
#pragma unroll
                for (int t = 0; t < 8; t++)
                    mma_tf32(acc[mt][t], af[mt], bf[t][0], bf[t][1]);
        }
        if (ch < 15) {
            uint32_t* aw = A0 + ((ch + 1) & 1) * 128 * PAD;
            uint32_t* bw = B0 + ((ch + 1) & 1) * 128 * PAD;
#pragma unroll
            for (int i = 0; i < 4; i++) {
                uint4 ua = {tf32r(ra[i].x), tf32r(ra[i].y), tf32r(ra[i].z), tf32r(ra[i].w)};
                *(uint4*)&aw[(row_b + 32 * i) * PAD + c4 * 4] = ua;
                uint4 ub = {tf32r(rb[i].x), tf32r(rb[i].y), tf32r(rb[i].z), tf32r(rb[i].w)};
                *(uint4*)&bw[(row_b + 32 * i) * PAD + c4 * 4] = ub;
            }
            __syncthreads();
            if (ch < 14) {
                const int kn = (ch + 2) * 32;
#pragma unroll
                for (int i = 0; i < 4; i++) {
                    ra[i] = *(const float4*)(Ag + (long)(32 * i) * 512 + kn);
                    rb[i] = *(const float4*)(Bg + (long)(32 * i) * 512 + kn);
                }
            }
        }
    }

    // Epilogue
#pragma unroll
    for (int mt = 0; mt < 2; mt++) {
        const int row0 = m0 + mw * 32 + mt * 16 + r;
#pragma unroll
        for (int t = 0; t < 8; t++) {
            const int col = n0 + nw * 64 + t * 8 + 2 * cq;
            float2 b2 = {0.f, 0.f};
            if (HAS_BIAS) b2 = *(const float2*)(bias + col);
            float2 v0 = {acc[mt][t][0] + b2.x, acc[mt][t][1] + b2.y};
            *(float2*)(C + (long)row0 * N + col) = v0;
            float2 v1 = {acc[mt][t][2] + b2.x, acc[mt][t][3] + b2.y};
            *(float2*)(C + (long)(row0 + 8) * N + col) = v1;
        }
    }
}

// ---------------------------------------------------------------------------
// Flash attention, tf32 mma.sync. 64-query tile, 128 thr (4 warps x m16).
// S and O accumulators in mma C-fragment layout; softmax via 4-lane shuffles.
// Smem: Qs/Ks/Ps [64][68], Vs [64][72] (conflict-free B-frag loads).
// ---------------------------------------------------------------------------
__global__ void __launch_bounds__(128)
flash_mma_kernel(const float* __restrict__ qkv, float* __restrict__ attn_out)
{
    extern __shared__ float fsm[];
    uint32_t* const Qb = (uint32_t*)fsm;                 // [64][68]
    uint32_t* const Kb = (uint32_t*)fsm + 64 * 68;       // [64][68]
    uint32_t* const Pb = (uint32_t*)fsm + 2 * 64 * 68;   // [64][68]
    uint32_t* const Vb = (uint32_t*)fsm + 3 * 64 * 68;   // [64][72]

    const int tid = threadIdx.x, lane = tid & 31, w = tid >> 5;
    const int r = lane >> 2, cq = lane & 3;
    const int bh = blockIdx.y, b = bh >> 3, h = bh & 7;
    const int q0 = blockIdx.x * 64;
    const float* base = qkv + (long)b * T * QKV_STRIDE + h * HK;

    // Loader: c4 = tid&15 (const), rows tid>>4 + 8*i
    const int c4 = tid & 15, rowq = tid >> 4;

    // Load Q tile (rounded to tf32); visible after first loop-top sync.
#pragma unroll
    for (int i = 0; i < 8; i++) {
        const int row = rowq + 8 * i;
        float4 v = *(const float4*)(base + (long)(q0 + row) * QKV_STRIDE + c4 * 4);
        uint4 u = {tf32r(v.x), tf32r(v.y), tf32r(v.z), tf32r(v.w)};
        *(uint4*)&Qb[row * 68 + c4 * 4] = u;
    }

    float m0_ = -1e30f, m1_ = -1e30f, l0_ = 0.f, l1_ = 0.f;
    float oacc[8][4] = {};
    const int ntiles = blockIdx.x + 1;
    const int r0 = w * 16 + r;

    for (int t0 = 0; t0 < ntiles; t0++) {
        const long j0 = (long)t0 * 64;
        __syncthreads();   // prior readers of Ks/Vs done; Q visible on t0=0
        {
            const float* kb = base + D;
            const float* vb = base + 2 * D;
#pragma unroll
            for (int i = 0; i < 8; i++) {
                const int row = rowq + 8 * i;
                float4 kv = *(const float4*)(kb + (j0 + row) * QKV_STRIDE + c4 * 4);
                uint4 uk = {tf32r(kv.x), tf32r(kv.y), tf32r(kv.z), tf32r(kv.w)};
                *(uint4*)&Kb[row * 68 + c4 * 4] = uk;
                float4 vv = *(const float4*)(vb + (j0 + row) * QKV_STRIDE + c4 * 4);
                uint4 uv = {tf32r(vv.x), tf32r(vv.y), tf32r(vv.z), tf32r(vv.w)};
                *(uint4*)&Vb[row * 72 + c4 * 4] = uv;
            }
        }
        __syncthreads();

        // S = Q @ K^T
        float s[8][4] = {};
#pragma unroll
        for (int kt = 0; kt < 8; kt++) {
            const int k0 = kt * 8;
            uint32_t a[4];
            a[0] = Qb[r0 * 68 + k0 + cq];
            a[1] = Qb[(r0 + 8) * 68 + k0 + cq];
            a[2] = Qb[r0 * 68 + k0 + cq + 4];
            a[3] = Qb[(r0 + 8) * 68 + k0 + cq + 4];
#pragma unroll
            for (int t = 0; t < 8; t++) {
                const uint32_t b0 = Kb[(t * 8 + r) * 68 + k0 + cq];
                const uint32_t b1 = Kb[(t * 8 + r) * 68 + k0 + cq + 4];
                mma_tf32(s[t], a, b0, b1);
            }
        }

        // scale + causal mask (diag tile only)
        const bool diag = (j0 == q0);
#pragma unroll
        for (int t = 0; t < 8; t++) {
            s[t][0] *= 0.125f; s[t][1] *= 0.125f;
            s[t][2] *= 0.125f; s[t][3] *= 0.125f;
            if (diag) {
                const int j = t * 8 + 2 * cq;
                if (j     > r0)     s[t][0] = -1e30f;
                if (j + 1 > r0)     s[t][1] = -1e30f;
                if (j     > r0 + 8) s[t][2] = -1e30f;
                if (j + 1 > r0 + 8) s[t][3] = -1e30f;
            }
        }

        // online softmax (rows r0, r0+8; 4 lanes share a row)
        float rm0 = -1e30f, rm1 = -1e30f;
#pragma unroll
        for (int t = 0; t < 8; t++) {
            rm0 = fmaxf(rm0, fmaxf(s[t][0], s[t][1]));
            rm1 = fmaxf(rm1, fmaxf(s[t][2], s[t][3]));
        }
        rm0 = fmaxf(rm0, __shfl_xor_sync(0xffffffffu, rm0, 1));
        rm0 = fmaxf(rm0, __shfl_xor_sync(0xffffffffu, rm0, 2));
        rm1 = fmaxf(rm1, __shfl_xor_sync(0xffffffffu, rm1, 1));
        rm1 = fmaxf(rm1, __shfl_xor_sync(0xffffffffu, rm1, 2));
        const float nm0 = fmaxf(m0_, rm0), nm1 = fmaxf(m1_, rm1);
        const float al0 = __expf(m0_ - nm0), al1 = __expf(m1_ - nm1);
        m0_ = nm0; m1_ = nm1;

        float rs0 = 0.f, rs1 = 0.f;
#pragma unroll
        for (int t = 0; t < 8; t++) {
            const float p0 = __expf(s[t][0] - nm0);
            const float p1 = __expf(s[t][1] - nm0);
            const float p2 = __expf(s[t][2] - nm1);
            const float p3 = __expf(s[t][3] - nm1);
            rs0 += p0 + p1; rs1 += p2 + p3;
            const int j = t * 8 + 2 * cq;
            Pb[r0 * 68 + j]       = tf32r(p0);
            Pb[r0 * 68 + j + 1]   = tf32r(p1);
            Pb[(r0 + 8) * 68 + j]     = tf32r(p2);
            Pb[(r0 + 8) * 68 + j + 1] = tf32r(p3);
        }
        rs0 += __shfl_xor_sync(0xffffffffu, rs0, 1);
        rs0 += __shfl_xor_sync(0xffffffffu, rs0, 2);
        rs1 += __shfl_xor_sync(0xffffffffu, rs1, 1);
        rs1 += __shfl_xor_sync(0xffffffffu, rs1, 2);
        l0_ = l0_ * al0 + rs0;
        l1_ = l1_ * al1 + rs1;
#pragma unroll
        for (int t = 0; t < 8; t++) {
            oacc[t][0] *= al0; oacc[t][1] *= al0;
            oacc[t][2] *= al1; oacc[t][3] *= al1;
        }
        __syncwarp();   // Ps is warp-private: cross-lane visibility only

        // O += P @ V
#pragma unroll
        for (int kt = 0; kt < 8; kt++) {
            const int k0 = kt * 8;
            uint32_t a[4];
            a[0] = Pb[r0 * 68 + k0 + cq];
            a[1] = Pb[(r0 + 8) * 68 + k0 + cq];
            a[2] = Pb[r0 * 68 + k0 + cq + 4];
            a[3] = Pb[(r0 + 8) * 68 + k0 + cq + 4];
#pragma unroll
            for (int t = 0; t < 8; t++) {
                const uint32_t b0 = Vb[(k0 + cq) * 72 + t * 8 + r];
                const uint32_t b1 = Vb[(k0 + cq + 4) * 72 + t * 8 + r];
                mma_tf32(oacc[t], a, b0, b1);
            }
        }
    }

    // Epilogue: normalize + write [B,T,H*K]
    const float inv0 = 1.f / l0_, inv1 = 1.f / l1_;
    float* ob = attn_out + ((long)b * T + q0) * D + h * HK;
#pragma unroll
    for (int t = 0; t < 8; t++) {
        const int col = t * 8 + 2 * cq;
        float2 v0 = {oacc[t][0] * inv0, oacc[t][1] * inv0};
        *(float2*)(ob + (long)r0 * D + col) = v0;
        float2 v1 = {oacc[t][2] * inv1, oacc[t][3] * inv1};
        *(float2*)(ob + (long)(r0 + 8) * D + col) = v1;
    }
}

// ---------------------------------------------------------------------------
extern "C" void kernel_launch(void* const* d_in, const int* in_sizes, int n_in,
                              void* d_out, int out_size)
{
    (void)out_size;
    const float *x = nullptr, *w_qkv = nullptr, *w_proj = nullptr, *b_proj = nullptr;
    for (int i = 0; i < n_in; i++) {
        switch (in_sizes[i]) {
            case MROWS * D: x      = (const float*)d_in[i]; break; // 4194304
            case 3 * D * D: w_qkv  = (const float*)d_in[i]; break; // 786432
            case D * D:     w_proj = (const float*)d_in[i]; break; // 262144
            case D:         b_proj = (const float*)d_in[i]; break; // 512
        }
    }
    float* out = (float*)d_out;

    float* qkv_buf = nullptr;
    float* attn_buf = nullptr;
    cudaGetSymbolAddress((void**)&qkv_buf, g_qkv);
    cudaGetSymbolAddress((void**)&attn_buf, g_attn);

    const int gemm_smem = 4 * 128 * 36 * 4;            // 73728
    const int attn_smem = (3 * 64 * 68 + 64 * 72) * 4; // 70656
    cudaFuncSetAttribute(gemm_mma_kernel<false>,
                         cudaFuncAttributeMaxDynamicSharedMemorySize, gemm_smem);
    cudaFuncSetAttribute(gemm_mma_kernel<true>,
                         cudaFuncAttributeMaxDynamicSharedMemorySize, gemm_smem);
    cudaFuncSetAttribute(flash_mma_kernel,
                         cudaFuncAttributeMaxDynamicSharedMemorySize, attn_smem);

    // 1) QKV projection: [8192,1536] = x @ w_qkv^T
    {
        dim3 grid(3 * D / 128, MROWS / 128);   // (12, 64)
        gemm_mma_kernel<false><<<grid, 256, gemm_smem>>>(x, w_qkv, nullptr,
                                                         qkv_buf, 3 * D);
    }
    // 2) Causal flash attention (tf32 mma)
    {
        dim3 grid(T / 64, Bb * Hh);            // (32, 32)
        flash_mma_kernel<<<grid, 128, attn_smem>>>(qkv_buf, attn_buf);
    }
    // 3) Output projection + bias
    {
        dim3 grid(D / 128, MROWS / 128);       // (4, 64)
        gemm_mma_kernel<true><<<grid, 256, gemm_smem>>>(attn_buf, w_proj, b_proj,
                                                        out, D);
    }
}